// round 3
// baseline (speedup 1.0000x reference)
#include <cuda_runtime.h>
#include <math_constants.h>

// Problem geometry (fixed by the reference):
//   queries/keys/values: [1, 32, 8, 32] fp32 -> 8192 floats each
//   segment length Ls=4 -> 8 segments of 1024 contiguous floats
//   dists[i][j] = exact DTW(|a-b| cost) between q-seg i and k-seg j (1024x1024 DP)
//   A = softmax(0.5 * dists, axis=-1) (8x8); out = A @ value-segments

#define N_SEG    8
#define SEG_LEN  1024
#define C_COLS   8
#define R_ROWS   8
#define P_THR    128
#define N_BLK    (SEG_LEN / R_ROWS)            // 128 row-blocks
#define SKEW_W   4                             // extra pipeline skew per warp seam
#define MAX_SIG  (P_THR - 1 + SKEW_W * 3)      // 139
#define N_STEPS  (N_BLK + MAX_SIG)             // 267
#define SUPER    4                             // steps per __syncthreads
#define NSUPER   ((N_STEPS + SUPER - 1) / SUPER) // 67 -> 268 executed steps
#define RING     16                            // seam ring slots (power of 2)

__device__ float        g_dists[N_SEG * N_SEG];
__device__ unsigned int g_count = 0;           // self-resetting via atomicInc wrap

// One CTA per (qi, kj) pair. Pipelined 8x8 register-tile DTW.
// Thread t owns columns [8t, 8t+8); skew sigma(t) = t + 4*warp(t).
// At step s, thread t processes row-block b = s - sigma(t).
// Intra-warp boundary handoff: __shfl_up of the tile's 8 right-boundary values
// (produced at step s, consumed by the right neighbor at s+1).
// Warp seams have dependency slack 5 (skew gap), so a CTA barrier every
// SUPER=4 steps suffices; seam values cross via a 16-slot smem ring.
__global__ __launch_bounds__(P_THR, 1)
void dtw_kernel(const float* __restrict__ q, const float* __restrict__ k,
                const float* __restrict__ values, float* __restrict__ out_g) {
    const int qi = blockIdx.x;
    const int kj = blockIdx.y;
    const float* __restrict__ xrow = q + qi * SEG_LEN;
    const float* __restrict__ ycol = k + kj * SEG_LEN;

    __shared__ float  sx[SEG_LEN];
    __shared__ float4 ring[3][RING][2];        // [seam][slot][2 x float4]
    __shared__ float  sA[N_SEG][N_SEG];        // epilogue softmax weights
    __shared__ unsigned s_last;

    const int t    = threadIdx.x;
    const int lane = t & 31;
    const int warp = t >> 5;
    const int sigma = t + SKEW_W * warp;
    const float INF = CUDART_INF_F;

    for (int i = t; i < SEG_LEN; i += P_THR) sx[i] = xrow[i];

    float y[C_COLS];
    {
        const float4* y4 = reinterpret_cast<const float4*>(ycol + t * C_COLS);
        float4 a = y4[0], b = y4[1];
        y[0]=a.x; y[1]=a.y; y[2]=a.z; y[3]=a.w;
        y[4]=b.x; y[5]=b.y; y[6]=b.z; y[7]=b.w;
    }

    float prev[C_COLS];                        // d[r-1, base..base+7]
    float lv[R_ROWS];                          // left-neighbor boundary values
    float ov[R_ROWS];                          // this tile's right-boundary values
#pragma unroll
    for (int j = 0; j < C_COLS; j++) { prev[j] = INF; lv[j] = INF; ov[j] = 0.0f; }
    float carry = (t == 0) ? 0.0f : INF;       // d[r0-1, base-1] entering a block

    __syncthreads();

    int s = 0;
    for (int sup = 0; sup < NSUPER; sup++) {
#pragma unroll
        for (int u = 0; u < SUPER; u++, s++) {
            const int b = s - sigma;
            if (0 <= b && b < N_BLK) {
                if (t == 0) {
#pragma unroll
                    for (int j = 0; j < R_ROWS; j++) lv[j] = INF;
                } else if (lane == 0) {
                    // seam consumer: value produced by warp-1 lane 31 at step s-5
                    const int slot = (s - 5) & (RING - 1);
                    float4 a = ring[warp - 1][slot][0];
                    float4 c = ring[warp - 1][slot][1];
                    lv[0]=a.x; lv[1]=a.y; lv[2]=a.z; lv[3]=a.w;
                    lv[4]=c.x; lv[5]=c.y; lv[6]=c.z; lv[7]=c.w;
                }

                float xr[R_ROWS];
                {
                    const float4* x4 = reinterpret_cast<const float4*>(sx + b * R_ROWS);
                    float4 a = x4[0], c = x4[1];
                    xr[0]=a.x; xr[1]=a.y; xr[2]=a.z; xr[3]=a.w;
                    xr[4]=c.x; xr[5]=c.y; xr[6]=c.z; xr[7]=c.w;
                }

#pragma unroll
                for (int rr = 0; rr < R_ROWS; rr++) {
                    float left = lv[rr];
                    float dpr  = (rr == 0) ? carry : lv[rr - 1];
                    const float x = xr[rr];
#pragma unroll
                    for (int j = 0; j < C_COLS; j++) {
                        const float c = fabsf(x - y[j]);
                        const float a = fminf(prev[j], dpr);
                        const float d = c + fminf(a, left);
                        dpr     = prev[j];
                        prev[j] = d;
                        left    = d;
                    }
                    ov[rr] = left;
                }
                carry = lv[R_ROWS - 1];

                if (lane == 31 && warp < 3) {  // seam producer
                    const int slot = s & (RING - 1);
                    ring[warp][slot][0] = make_float4(ov[0], ov[1], ov[2], ov[3]);
                    ring[warp][slot][1] = make_float4(ov[4], ov[5], ov[6], ov[7]);
                }
            }
            // handoff: all lanes participate (convergence point)
#pragma unroll
            for (int j = 0; j < R_ROWS; j++)
                lv[j] = __shfl_up_sync(0xffffffffu, ov[j], 1);
        }
        __syncthreads();
    }

    if (t == P_THR - 1)
        g_dists[qi * N_SEG + kj] = prev[C_COLS - 1];   // d[1023, 1023]

    // ---- fused epilogue: last CTA to finish does softmax + A @ V ----
    __threadfence();
    if (t == 0) s_last = atomicInc(&g_count, N_SEG * N_SEG - 1);
    __syncthreads();
    if (s_last != N_SEG * N_SEG - 1) return;
    __threadfence();

    // threads 0..7 each compute one softmax row into smem
    if (t < N_SEG) {
        float l[N_SEG];
        float m = -INF;
#pragma unroll
        for (int j = 0; j < N_SEG; j++) {
            l[j] = 0.5f * g_dists[t * N_SEG + j];      // scale = 1/sqrt(4)
            m = fmaxf(m, l[j]);
        }
        float ssum = 0.0f;
#pragma unroll
        for (int j = 0; j < N_SEG; j++) {
            l[j] = expf(l[j] - m);
            ssum += l[j];
        }
        const float inv = 1.0f / ssum;
#pragma unroll
        for (int j = 0; j < N_SEG; j++) sA[t][j] = l[j] * inv;
    }
    __syncthreads();

    // 8192 floats = 2048 float4; 128 threads x 16 each
    const float4* v4 = reinterpret_cast<const float4*>(values);
    float4* o4 = reinterpret_cast<float4*>(out_g);
#pragma unroll
    for (int n = 0; n < 16; n++) {
        const int g = t + n * P_THR;                   // float4 index
        const int i = g >> 8;                          // segment (256 float4/seg)
        const int c = g & 255;
        float4 acc = make_float4(0.f, 0.f, 0.f, 0.f);
#pragma unroll
        for (int j = 0; j < N_SEG; j++) {
            const float w = sA[i][j];
            const float4 v = v4[j * 256 + c];
            acc.x += w * v.x;
            acc.y += w * v.y;
            acc.z += w * v.z;
            acc.w += w * v.w;
        }
        o4[g] = acc;
    }
}

extern "C" void kernel_launch(void* const* d_in, const int* in_sizes, int n_in,
                              void* d_out, int out_size) {
    const float* queries = (const float*)d_in[0];
    const float* keys    = (const float*)d_in[1];
    const float* values  = (const float*)d_in[2];
    float* out = (float*)d_out;

    dim3 grid(N_SEG, N_SEG);
    dtw_kernel<<<grid, P_THR>>>(queries, keys, values, out);
}

// round 4
// speedup vs baseline: 1.2185x; 1.2185x over previous
#include <cuda_runtime.h>
#include <math_constants.h>

// queries/keys/values: 8192 fp32 each; 8 segments of 1024 contiguous floats.
// dists[i][j] = exact DTW(|a-b|) between q-seg i and k-seg j (1024x1024 DP).
// A = softmax(0.5*dists, axis=-1); out = A @ value-segments.

#define N_SEG    8
#define SEG_LEN  1024
#define C_COLS   8
#define R_ROWS   8
#define P_THR    128
#define N_BLK    (SEG_LEN / R_ROWS)          // 128 row-blocks
#define SKEW_W   4                           // extra skew per warp seam
#define SIG_MAX  (P_THR - 1 + SKEW_W * 3)    // 139
#define N_STEPS  (N_BLK + SIG_MAX)           // 267
#define SUPER    4                           // steps per __syncthreads
#define NSUPER   ((N_STEPS + SUPER - 1) / SUPER)  // 67 (268 executed steps)
#define RING     16

__device__ float        g_dists[N_SEG * N_SEG];
__device__ unsigned int g_count = 0;         // self-resetting via atomicInc wrap

// One CTA per (qi,kj). Branch-free pipelined 8x8 register-tile DTW.
// Thread t owns cols [8t,8t+8); skew sigma = t + 4*warp; step s processes
// row-block b = s - sigma. INF is a fixed point of the recurrence, so
// out-of-range threads run the same code on INF state and produce exactly the
// correct virtual boundaries (rows clamped for the smem read only).
// Intra-warp handoff: shfl_up, split around the row 4-7 compute so latency is
// fully hidden. Warp seams: 16-slot smem ring, consumer prefetches slot s-4
// (for step s+1); barrier every 4 steps guarantees visibility.
__global__ __launch_bounds__(P_THR, 1)
void dtw_kernel(const float* __restrict__ q, const float* __restrict__ k,
                const float* __restrict__ values, float* __restrict__ out_g) {
    const int qi = blockIdx.x;
    const int kj = blockIdx.y;
    const float* __restrict__ xrow = q + qi * SEG_LEN;
    const float* __restrict__ ycol = k + kj * SEG_LEN;

    __shared__ float  sx[SEG_LEN];
    __shared__ float4 ring[3][RING][2];
    __shared__ float  sA[N_SEG][N_SEG];
    __shared__ unsigned s_last;

    const int t    = threadIdx.x;
    const int lane = t & 31;
    const int warp = t >> 5;
    const int sigma = t + SKEW_W * warp;
    const float INF = CUDART_INF_F;

    for (int i = t; i < SEG_LEN / 4; i += P_THR)
        reinterpret_cast<float4*>(sx)[i] = reinterpret_cast<const float4*>(xrow)[i];
    {
        const float4 inf4 = make_float4(INF, INF, INF, INF);
        float4* rp = &ring[0][0][0];
        for (int i = t; i < 3 * RING * 2; i += P_THR) rp[i] = inf4;
    }

    float y[C_COLS];
    {
        const float4* y4 = reinterpret_cast<const float4*>(ycol + t * C_COLS);
        float4 a = y4[0], b = y4[1];
        y[0]=a.x; y[1]=a.y; y[2]=a.z; y[3]=a.w;
        y[4]=b.x; y[5]=b.y; y[6]=b.z; y[7]=b.w;
    }

    float prev[C_COLS], lv[R_ROWS], ov[R_ROWS];
#pragma unroll
    for (int j = 0; j < 8; j++) { prev[j] = INF; lv[j] = INF; ov[j] = INF; }
    float carry = (t == 0) ? 0.0f : INF;     // d[r0-1, base-1] entering a block
    float res = 0.0f;

    __syncthreads();

    float xr[R_ROWS];
    {   // preload rows for step 0: b = -sigma -> clamps to block 0
        const float4* x4 = reinterpret_cast<const float4*>(sx);
        float4 a = x4[0], b = x4[1];
        xr[0]=a.x; xr[1]=a.y; xr[2]=a.z; xr[3]=a.w;
        xr[4]=b.x; xr[5]=b.y; xr[6]=b.z; xr[7]=b.w;
    }

    int s = 0;
    for (int sup = 0; sup < NSUPER; sup++) {
#pragma unroll
        for (int u = 0; u < SUPER; u++, s++) {
            const int b = s - sigma;

            // rows 0..3
#pragma unroll
            for (int rr = 0; rr < 4; rr++) {
                float left = lv[rr];
                float dpr  = (rr == 0) ? carry : lv[rr - 1];
                const float x = xr[rr];
#pragma unroll
                for (int j = 0; j < C_COLS; j++) {
                    const float c = fabsf(x - y[j]);
                    const float a = fminf(prev[j], dpr);
                    const float d = c + fminf(a, left);
                    dpr     = prev[j];
                    prev[j] = d;
                    left    = d;
                }
                ov[rr] = left;
            }
            const float lv3 = lv[3];
            lv[0] = __shfl_up_sync(0xffffffffu, ov[0], 1);
            lv[1] = __shfl_up_sync(0xffffffffu, ov[1], 1);
            lv[2] = __shfl_up_sync(0xffffffffu, ov[2], 1);
            lv[3] = __shfl_up_sync(0xffffffffu, ov[3], 1);

            // prefetch x for next step (clamped; garbage rows are harmless)
            const int bn = s + 1 - sigma;
            const int rn = min(max(bn, 0), N_BLK - 1) * R_ROWS;
            const float4 xa = *reinterpret_cast<const float4*>(sx + rn);
            const float4 xb = *reinterpret_cast<const float4*>(sx + rn + 4);

            // rows 4..7
#pragma unroll
            for (int rr = 4; rr < 8; rr++) {
                float left = lv[rr];
                float dpr  = (rr == 4) ? lv3 : lv[rr - 1];
                const float x = xr[rr];
#pragma unroll
                for (int j = 0; j < C_COLS; j++) {
                    const float c = fabsf(x - y[j]);
                    const float a = fminf(prev[j], dpr);
                    const float d = c + fminf(a, left);
                    dpr     = prev[j];
                    prev[j] = d;
                    left    = d;
                }
                ov[rr] = left;
            }

            res = (b == N_BLK - 1) ? ov[7] : res;   // d[1023, base+7]

            if (lane == 31 && warp < 3) {           // seam producer
                const int slot = s & (RING - 1);
                ring[warp][slot][0] = make_float4(ov[0], ov[1], ov[2], ov[3]);
                ring[warp][slot][1] = make_float4(ov[4], ov[5], ov[6], ov[7]);
            }

            carry = lv[7];
            lv[4] = __shfl_up_sync(0xffffffffu, ov[4], 1);
            lv[5] = __shfl_up_sync(0xffffffffu, ov[5], 1);
            lv[6] = __shfl_up_sync(0xffffffffu, ov[6], 1);
            lv[7] = __shfl_up_sync(0xffffffffu, ov[7], 1);

            // seam consumer prefetch for step s+1 (slot s-4: behind >=1 barrier)
            if (lane == 0) {
                if (warp != 0) {
                    const int slot = (s - 4) & (RING - 1);
                    float4 a = ring[warp - 1][slot][0];
                    float4 c = ring[warp - 1][slot][1];
                    lv[0]=a.x; lv[1]=a.y; lv[2]=a.z; lv[3]=a.w;
                    lv[4]=c.x; lv[5]=c.y; lv[6]=c.z; lv[7]=c.w;
                } else {
#pragma unroll
                    for (int j = 0; j < 8; j++) lv[j] = INF;  // global left edge
                }
            }

            xr[0]=xa.x; xr[1]=xa.y; xr[2]=xa.z; xr[3]=xa.w;
            xr[4]=xb.x; xr[5]=xb.y; xr[6]=xb.z; xr[7]=xb.w;
        }
        __syncthreads();
    }

    if (t == P_THR - 1) g_dists[qi * N_SEG + kj] = res;

    // ---- fused epilogue: last CTA to arrive does softmax + A @ V ----
    __threadfence();
    if (t == 0) s_last = atomicInc(&g_count, N_SEG * N_SEG - 1);
    __syncthreads();
    if (s_last != N_SEG * N_SEG - 1) return;
    __threadfence();

    if (t < N_SEG) {
        float l[N_SEG];
        float m = -INF;
#pragma unroll
        for (int j = 0; j < N_SEG; j++) {
            l[j] = 0.5f * g_dists[t * N_SEG + j];   // scale = 1/sqrt(4)
            m = fmaxf(m, l[j]);
        }
        float ssum = 0.0f;
#pragma unroll
        for (int j = 0; j < N_SEG; j++) {
            l[j] = expf(l[j] - m);
            ssum += l[j];
        }
        const float inv = 1.0f / ssum;
#pragma unroll
        for (int j = 0; j < N_SEG; j++) sA[t][j] = l[j] * inv;
    }
    __syncthreads();

    const float4* v4 = reinterpret_cast<const float4*>(values);
    float4* o4 = reinterpret_cast<float4*>(out_g);
#pragma unroll
    for (int n = 0; n < 16; n++) {
        const int g = t + n * P_THR;                // float4 index (2048 total)
        const int i = g >> 8;                       // segment (256 float4/seg)
        const int c = g & 255;
        float4 acc = make_float4(0.f, 0.f, 0.f, 0.f);
#pragma unroll
        for (int j = 0; j < N_SEG; j++) {
            const float w = sA[i][j];
            const float4 v = v4[j * 256 + c];
            acc.x += w * v.x;
            acc.y += w * v.y;
            acc.z += w * v.z;
            acc.w += w * v.w;
        }
        o4[g] = acc;
    }
}

extern "C" void kernel_launch(void* const* d_in, const int* in_sizes, int n_in,
                              void* d_out, int out_size) {
    const float* queries = (const float*)d_in[0];
    const float* keys    = (const float*)d_in[1];
    const float* values  = (const float*)d_in[2];
    float* out = (float*)d_out;

    dim3 grid(N_SEG, N_SEG);
    dtw_kernel<<<grid, P_THR>>>(queries, keys, values, out);
}